// round 13
// baseline (speedup 1.0000x reference)
#include <cuda_runtime.h>
#include <cstdint>

#define ORD   24
#define TLEN  168
#define DD    512
#define SS    336
#define BB    256
#define NTS   21              // n-tiles of 8 t
#define LSTR  172             // smem lane stride in floats (bank-conflict-free)
#define NUNIT 4096            // work units = batch x d-quarter x warp-quarter
#define GRIDB 592             // 148 SMs x 4 CTAs, one persistent wave
#define WARPS (GRIDB * 4)     // 2368 warps; units >= this are stolen

__device__ int g_counter = 0;   // work-steal counter (self-resets per launch)
__device__ int g_done    = 0;

// ---------------------------------------------------------------------------
__device__ __forceinline__ uint32_t to_tf32(float v) {
    uint32_t u;
    asm("cvt.rna.tf32.f32 %0, %1;" : "=r"(u) : "f"(v));
    return u;
}

// m16n8k8 tf32 MMA (sm_80+ base feature; valid on compute_103).
__device__ __forceinline__ void mma8(float& d0, float& d1, float& d2, float& d3,
                                     uint32_t a0, uint32_t a1, uint32_t a2,
                                     uint32_t a3, uint32_t b0, uint32_t b1) {
    asm volatile(
        "mma.sync.aligned.m16n8k8.row.col.f32.tf32.tf32.f32 "
        "{%0,%1,%2,%3}, {%4,%5,%6,%7}, {%8,%9}, {%0,%1,%2,%3};"
        : "+f"(d0), "+f"(d1), "+f"(d2), "+f"(d3)
        : "r"(a0), "r"(a1), "r"(a2), "r"(a3), "r"(b0), "r"(b1));
}

// ---------------------------------------------------------------------------
// Fused persistent kernel, warp-autonomous after the prologue.
//   Prologue (threads 0..31): thread j runs the exact-fp32 coefficient
//   recurrence for column j (j==24 = bias column; j>=25 emit zeros), writing
//   3xTF32 hi/lo tables DIRECTLY IN FRAGMENT ORDER:
//     lane = (t&7)*4 + (j&3),  p = (j>>3)*2 + ((j>>2)&1)
//     sB[lane*LSTR + (t>>3)*8 + p]
//   so the mainloop fetches a warp's whole B fragment as 2 LDS.128 per table.
//   Mainloop: unit = (batch, dq, wq). Warp owns d rows [dq*128+wq*32, +32)
//   x all 168 t. A fragments (ctx hi/lo) straight from global. 3xTF32 with
//   separate accumulators: D = Ah*Bh + Ah*Bl + Al*Bh. No CTA syncs.
// ---------------------------------------------------------------------------
__global__ void __launch_bounds__(128, 4)
ar_fused_kernel(const float* __restrict__ x, const float* __restrict__ W,
                const float* __restrict__ bptr, float* __restrict__ out) {
    __shared__ __align__(16) float sBh[32 * LSTR];   // 22.0 KB
    __shared__ __align__(16) float sBl[32 * LSTR];   // 22.0 KB

    const int tid  = threadIdx.x;
    const int warp = tid >> 5;
    const int lane = tid & 31;
    const int g    = lane >> 2;          // groupID 0..7
    const int tg   = lane & 3;           // thread-in-group 0..3

    // ---- coef prologue (threads 0..31) ----
    if (tid < 32) {
        const int j = tid;
        const int pl = (j >> 3) * 2 + ((j >> 2) & 1);  // slot within 8-vec
        const int jl = j & 3;                          // tg of target lane

        if (j >= 25) {
            for (int t = 0; t < TLEN; t++) {
                const int ln = (t & 7) * 4 + jl;
                const int of = ln * LSTR + (t >> 3) * 8 + pl;
                sBh[of] = 0.0f;
                sBl[of] = 0.0f;
            }
        } else {
            float w[ORD];
#pragma unroll
            for (int i = 0; i < ORD; i++) w[i] = W[i];
            const float bias = bptr[0];

            float m[ORD];
#pragma unroll
            for (int i = 0; i < ORD; i++)
                m[i] = (j < ORD && i == j) ? 1.0f : 0.0f;

            for (int t = 0; t < TLEN; t++) {
                float p[24];
#pragma unroll
                for (int i = 0; i < 23; i++) p[i] = w[i] * m[i];
                p[23] = 0.0f;
#pragma unroll
                for (int k = 0; k < 12; k++) p[k] = p[2 * k] + p[2 * k + 1];
#pragma unroll
                for (int k = 0; k < 6; k++)  p[k] = p[2 * k] + p[2 * k + 1];
#pragma unroll
                for (int k = 0; k < 3; k++)  p[k] = p[2 * k] + p[2 * k + 1];
                float y = (p[0] + p[1]) + p[2];
                y = fmaf(w[23], m[23], y);
                if (j == 24) y += bias;

                const float hi = __uint_as_float(to_tf32(y));
                const int ln = (t & 7) * 4 + jl;
                const int of = ln * LSTR + (t >> 3) * 8 + pl;
                sBh[of] = hi;
                sBl[of] = __uint_as_float(to_tf32(y - hi));

#pragma unroll
                for (int i = 0; i < ORD - 1; i++) m[i] = m[i + 1];
                m[ORD - 1] = y;          // recurrence stays full fp32
            }
        }
    }
    __syncthreads();                     // the ONLY CTA sync

    const float4* bh4 = reinterpret_cast<const float4*>(&sBh[lane * LSTR]);
    const float4* bl4 = reinterpret_cast<const float4*>(&sBl[lane * LSTR]);

    int u = blockIdx.x * 4 + warp;       // first unit pre-assigned

    for (;;) {
        const int batch = u >> 4, dq = (u >> 2) & 3, wq = u & 3;
        const float* xb =
            x + ((size_t)batch * SS + (SS - ORD)) * DD + dq * 128 + wq * 32;

        // ---- A fragments straight from global (one-time per unit) ----
        uint32_t ah[2][4][4], al[2][3][4];
#pragma unroll
        for (int mi = 0; mi < 2; mi++) {
            const int r0 = mi * 16 + g;
            const int r1 = r0 + 8;
#pragma unroll
            for (int kc = 0; kc < 3; kc++) {
                const int ka = kc * 8 + tg, kb = ka + 4;
                const float v0 = xb[(size_t)ka * DD + r0];
                const float v1 = xb[(size_t)ka * DD + r1];
                const float v2 = xb[(size_t)kb * DD + r0];
                const float v3 = xb[(size_t)kb * DD + r1];
                const uint32_t h0 = to_tf32(v0), h1 = to_tf32(v1);
                const uint32_t h2 = to_tf32(v2), h3 = to_tf32(v3);
                ah[mi][kc][0] = h0;
                ah[mi][kc][1] = h1;
                ah[mi][kc][2] = h2;
                ah[mi][kc][3] = h3;
                al[mi][kc][0] = to_tf32(v0 - __uint_as_float(h0));
                al[mi][kc][1] = to_tf32(v1 - __uint_as_float(h1));
                al[mi][kc][2] = to_tf32(v2 - __uint_as_float(h2));
                al[mi][kc][3] = to_tf32(v3 - __uint_as_float(h3));
            }
            const uint32_t one = (tg == 0) ? __float_as_uint(1.0f) : 0u;
            ah[mi][3][0] = one;          // bias column at k=24
            ah[mi][3][1] = one;
            ah[mi][3][2] = 0u;
            ah[mi][3][3] = 0u;
        }

        float* ob = out + (size_t)batch * TLEN * DD + dq * 128 + wq * 32;

        // ---- 21 n-tiles of 8 t ----
#pragma unroll 3
        for (int nt = 0; nt < NTS; nt++) {
            const int t0 = nt * 8;

            // B fragment: 4 LDS.128 (conflict-free by LSTR construction)
            const float4 h0 = bh4[nt * 2], h1 = bh4[nt * 2 + 1];
            const float4 l0 = bl4[nt * 2], l1 = bl4[nt * 2 + 1];
            const uint32_t bh[4][2] = {
                {__float_as_uint(h0.x), __float_as_uint(h0.y)},
                {__float_as_uint(h0.z), __float_as_uint(h0.w)},
                {__float_as_uint(h1.x), __float_as_uint(h1.y)},
                {__float_as_uint(h1.z), __float_as_uint(h1.w)}};
            const uint32_t bl[4][2] = {
                {__float_as_uint(l0.x), __float_as_uint(l0.y)},
                {__float_as_uint(l0.z), __float_as_uint(l0.w)},
                {__float_as_uint(l1.x), __float_as_uint(l1.y)},
                {__float_as_uint(l1.z), __float_as_uint(l1.w)}};

            // 6 independent accumulator chains, round-robin issue
            float aH0[4] = {0, 0, 0, 0}, aM0[4] = {0, 0, 0, 0},
                  aL0[4] = {0, 0, 0, 0};
            float aH1[4] = {0, 0, 0, 0}, aM1[4] = {0, 0, 0, 0},
                  aL1[4] = {0, 0, 0, 0};
#pragma unroll
            for (int kc = 0; kc < 4; kc++) {
                mma8(aH0[0], aH0[1], aH0[2], aH0[3],
                     ah[0][kc][0], ah[0][kc][1], ah[0][kc][2], ah[0][kc][3],
                     bh[kc][0], bh[kc][1]);
                mma8(aH1[0], aH1[1], aH1[2], aH1[3],
                     ah[1][kc][0], ah[1][kc][1], ah[1][kc][2], ah[1][kc][3],
                     bh[kc][0], bh[kc][1]);
                mma8(aM0[0], aM0[1], aM0[2], aM0[3],
                     ah[0][kc][0], ah[0][kc][1], ah[0][kc][2], ah[0][kc][3],
                     bl[kc][0], bl[kc][1]);
                mma8(aM1[0], aM1[1], aM1[2], aM1[3],
                     ah[1][kc][0], ah[1][kc][1], ah[1][kc][2], ah[1][kc][3],
                     bl[kc][0], bl[kc][1]);
                if (kc < 3) {            // kc=3 has all-zero A-lo
                    mma8(aL0[0], aL0[1], aL0[2], aL0[3],
                         al[0][kc][0], al[0][kc][1], al[0][kc][2],
                         al[0][kc][3], bh[kc][0], bh[kc][1]);
                    mma8(aL1[0], aL1[1], aL1[2], aL1[3],
                         al[1][kc][0], al[1][kc][1], al[1][kc][2],
                         al[1][kc][3], bh[kc][0], bh[kc][1]);
                }
            }

            const size_t tq = (size_t)(t0 + tg * 2) * DD;
            __stcs(ob + tq + g,           (aH0[0] + aM0[0]) + aL0[0]);
            __stcs(ob + tq + DD + g,      (aH0[1] + aM0[1]) + aL0[1]);
            __stcs(ob + tq + g + 8,       (aH0[2] + aM0[2]) + aL0[2]);
            __stcs(ob + tq + DD + g + 8,  (aH0[3] + aM0[3]) + aL0[3]);
            __stcs(ob + tq + g + 16,      (aH1[0] + aM1[0]) + aL1[0]);
            __stcs(ob + tq + DD + g + 16, (aH1[1] + aM1[1]) + aL1[1]);
            __stcs(ob + tq + g + 24,      (aH1[2] + aM1[2]) + aL1[2]);
            __stcs(ob + tq + DD + g + 24, (aH1[3] + aM1[3]) + aL1[3]);
        }

        // ---- warp-autonomous steal (no CTA sync) ----
        int nu;
        if (lane == 0) nu = WARPS + atomicAdd(&g_counter, 1);
        u = __shfl_sync(0xffffffffu, nu, 0);
        if (u >= NUNIT) break;
    }

    // ---- self-reset so each graph replay starts identically ----
    if (lane == 0) {
        const int d = atomicAdd(&g_done, 1);
        if (d == WARPS - 1) {
            atomicExch(&g_counter, 0);
            atomicExch(&g_done, 0);
        }
    }
}

// ---------------------------------------------------------------------------
extern "C" void kernel_launch(void* const* d_in, const int* in_sizes, int n_in,
                              void* d_out, int out_size) {
    const float* x = (const float*)d_in[0];   // [256, 336, 512] f32
    const float* W = (const float*)d_in[1];   // [24, 1] f32
    const float* b = (const float*)d_in[2];   // [1] f32
    float* out = (float*)d_out;               // [256, 168, 512] f32

    ar_fused_kernel<<<GRIDB, 128>>>(x, W, b, out);
}